// round 8
// baseline (speedup 1.0000x reference)
#include <cuda_runtime.h>
#include <stdint.h>

// Problem constants (match reference: B=1048576, Z_DIM=128, K=512)
#define ZDIM 128
#define KDIM 512
#define RPG 8                 // rows per group (one group = one warp-iteration)
#define NBLOCKS 456           // 152 SMs * 3 resident blocks
#define NTHREADS 128          // 4 warps/block

// Scratch for transposed a: at[k][d] = a[d][k].  512*128 floats = 256 KB.
__device__ float g_at[KDIM * ZDIM];

// ---------------------------------------------------------------------------
// Pre-pass: 32x32 smem-tiled transpose, coalesced both directions.
// ---------------------------------------------------------------------------
__global__ void transpose_a_kernel(const float* __restrict__ a) {
    __shared__ float tile[32][33];
    int kBase = blockIdx.x * 32;
    int dBase = blockIdx.y * 32;
    #pragma unroll
    for (int r = 0; r < 32; r += 8) {
        int d = dBase + threadIdx.y + r;
        int k = kBase + threadIdx.x;
        tile[threadIdx.y + r][threadIdx.x] = a[d * KDIM + k];
    }
    __syncthreads();
    #pragma unroll
    for (int r = 0; r < 32; r += 8) {
        int k = kBase + threadIdx.y + r;
        int d = dBase + threadIdx.x;
        g_at[k * ZDIM + d] = tile[threadIdx.x][threadIdx.y + r];
    }
}

// ---------------------------------------------------------------------------
// Persistent fused gather+axpy with register double-buffering.
// Each warp loops over groups of 8 rows (grid-stride). While storing group i,
// group i+1's 8 z-loads + 8 at-loads are already in flight, so reads never
// drain during store bursts (better DRAM R/W overlap).
// ---------------------------------------------------------------------------
struct Group {
    float4 zv[RPG];
    float4 av[RPG];
    float  scl[RPG];
};

__device__ __forceinline__ void load_group(Group& gb,
                                           const float4* __restrict__ z4,
                                           const int* __restrict__ labels_idx,
                                           const float* __restrict__ labels_scale,
                                           const float4* __restrict__ at4,
                                           long long row0, int lane) {
    int idx[RPG];
    #pragma unroll
    for (int r = 0; r < RPG; ++r) idx[r] = __ldg(&labels_idx[row0 + r]);
    #pragma unroll
    for (int r = 0; r < RPG; ++r) gb.scl[r] = __ldg(&labels_scale[row0 + r]);

    const size_t base = (size_t)row0 * (ZDIM / 4) + lane;
    #pragma unroll
    for (int r = 0; r < RPG; ++r)
        gb.zv[r] = __ldcs(&z4[base + (size_t)r * (ZDIM / 4)]);
    #pragma unroll
    for (int r = 0; r < RPG; ++r)
        gb.av[r] = __ldg(&at4[(size_t)idx[r] * (ZDIM / 4) + lane]);
}

__device__ __forceinline__ void store_group(const Group& gb,
                                            float4* __restrict__ out4,
                                            long long row0, int lane) {
    const size_t base = (size_t)row0 * (ZDIM / 4) + lane;
    #pragma unroll
    for (int r = 0; r < RPG; ++r) {
        float4 o;
        o.x = fmaf(gb.av[r].x, gb.scl[r], gb.zv[r].x);
        o.y = fmaf(gb.av[r].y, gb.scl[r], gb.zv[r].y);
        o.z = fmaf(gb.av[r].z, gb.scl[r], gb.zv[r].z);
        o.w = fmaf(gb.av[r].w, gb.scl[r], gb.zv[r].w);
        __stcs(&out4[base + (size_t)r * (ZDIM / 4)], o);
    }
}

__global__ void __launch_bounds__(NTHREADS, 3)
fused_gather_axpy_kernel(const float4* __restrict__ z4,
                         const int* __restrict__ labels_idx,
                         const float* __restrict__ labels_scale,
                         float4* __restrict__ out4,
                         int n_rows) {
    const int lane = threadIdx.x & 31;
    const long long warp_g = (long long)blockIdx.x * (NTHREADS / 32)
                             + (threadIdx.x >> 5);
    const long long total_warps = (long long)gridDim.x * (NTHREADS / 32);
    const long long n_groups = n_rows / RPG;

    const float4* __restrict__ at4 = reinterpret_cast<const float4*>(g_at);

    Group A, B;
    long long g = warp_g;

    if (g < n_groups) {
        load_group(A, z4, labels_idx, labels_scale, at4, g * RPG, lane);
        while (true) {
            // ping: A loaded; prefetch into B, then store A
            long long gn = g + total_warps;
            if (gn < n_groups)
                load_group(B, z4, labels_idx, labels_scale, at4, gn * RPG, lane);
            store_group(A, out4, g * RPG, lane);
            g = gn;
            if (g >= n_groups) break;

            // pong: B loaded; prefetch into A, then store B
            gn = g + total_warps;
            if (gn < n_groups)
                load_group(A, z4, labels_idx, labels_scale, at4, gn * RPG, lane);
            store_group(B, out4, g * RPG, lane);
            g = gn;
            if (g >= n_groups) break;
        }
    }

    // Tail rows (n_rows % RPG), handled by global warp 0 only.
    if (warp_g == 0) {
        for (long long r = n_groups * RPG; r < n_rows; ++r) {
            int   i = __ldg(&labels_idx[r]);
            float s = __ldg(&labels_scale[r]);
            size_t off = (size_t)r * (ZDIM / 4) + lane;
            float4 zvv = __ldcs(&z4[off]);
            float4 avv = __ldg(&at4[(size_t)i * (ZDIM / 4) + lane]);
            float4 o;
            o.x = fmaf(avv.x, s, zvv.x);
            o.y = fmaf(avv.y, s, zvv.y);
            o.z = fmaf(avv.z, s, zvv.z);
            o.w = fmaf(avv.w, s, zvv.w);
            __stcs(&out4[off], o);
        }
    }
}

extern "C" void kernel_launch(void* const* d_in, const int* in_sizes, int n_in,
                              void* d_out, int out_size) {
    const float* z     = (const float*)d_in[0];   // (B, 128) f32
    const float* a     = (const float*)d_in[1];   // (128, 512) f32
    const int*   idx   = (const int*)d_in[2];     // (B,) int32 on device
    const float* scale = (const float*)d_in[3];   // (B,) f32
    float*       out   = (float*)d_out;

    const int B = in_sizes[2];

    // 1) transpose a into L2-resident scratch
    {
        dim3 grid(KDIM / 32, ZDIM / 32);
        dim3 block(32, 8);
        transpose_a_kernel<<<grid, block>>>(a);
    }

    // 2) persistent fused gather + axpy with prefetch pipelining
    fused_gather_axpy_kernel<<<NBLOCKS, NTHREADS>>>(
        (const float4*)z, idx, scale, (float4*)out, B);
}